// round 4
// baseline (speedup 1.0000x reference)
#include <cuda_runtime.h>
#include <math.h>

#define BB 64
#define LL 2048
#define DD 256
#define KK 32
#define NCHUNK 8
#define CHUNK 256          // LL / NCHUNK
#define ST 64              // subtile rows
#define NSUB 4             // CHUNK / ST
#define NTH 256
#define XPAD 260           // 260 % 32 == 4 -> conflict-free patterns used below
#define WPAD 33
#define PPAD 33

// Scratch (no allocations allowed): flash partials per (batch, chunk)
__device__ float g_partC[BB * NCHUNK * KK * DD];   // 16 MB
__device__ float g_partM[BB * NCHUNK * KK];
__device__ float g_partS[BB * NCHUNK * KK];

__global__ __launch_bounds__(NTH, 2)
void fused_kernel(const float* __restrict__ X, const float* __restrict__ W) {
    extern __shared__ float smem[];
    float* Wt = smem;                  // [DD][WPAD]  W transposed: Wt[d*33 + k]
    float* Xs = Wt + DD * WPAD;        // [ST][XPAD]
    float* Ps = Xs + ST * XPAD;        // [ST][PPAD]  scores -> probs
    __shared__ float Sm[KK], Ss[KK], Sf[KK];

    const int b = blockIdx.y, c = blockIdx.x;
    const int t = threadIdx.x;
    const int lane = t & 31, w = t >> 5;
    const int kq = lane & 7, rr = lane >> 3;
    const int w4 = w * 4;

    // Stage W transposed (coalesced LDG, conflict-free STS via pad 33)
    for (int i = t; i < KK * DD; i += NTH) {
        int k = i >> 8, d = i & 255;
        Wt[d * WPAD + k] = W[i];
    }
    if (t < KK) { Sm[t] = -INFINITY; Ss[t] = 0.f; }

    // Accumulators: thread owns codes k = w4..w4+3, dims d = lane + 32*j
    float C[4][8];
    #pragma unroll
    for (int i = 0; i < 4; i++)
        #pragma unroll
        for (int j = 0; j < 8; j++) C[i][j] = 0.f;

    const int row0 = c * CHUNK;

    for (int sub = 0; sub < NSUB; sub++) {
        __syncthreads();   // previous accumulate finished reading Xs/Ps
        // ---- stage X subtile (64 x 256 fp32) with float4 ----
        {
            const float4* src = (const float4*)(X + ((size_t)b * LL + row0 + sub * ST) * DD);
            float4* dst = (float4*)Xs;
            #pragma unroll
            for (int i = t; i < ST * DD / 4; i += NTH) {
                int l = i >> 6, cpos = i & 63;
                dst[l * (XPAD / 4) + cpos] = src[i];
            }
        }
        __syncthreads();
        // ---- scoring: thread computes S[l0..l0+1][kq*4..kq*4+3] ----
        {
            const int l0 = w * 8 + rr * 2;
            float s0[4] = {0.f, 0.f, 0.f, 0.f};
            float s1[4] = {0.f, 0.f, 0.f, 0.f};
            const float* xr = Xs + l0 * XPAD;
            const float* Wc = Wt + kq * 4;
            #pragma unroll 4
            for (int d = 0; d < DD; d++) {
                float x0 = xr[d], x1 = xr[XPAD + d];
                const float* wrow = Wc + (size_t)d * WPAD;
                #pragma unroll
                for (int i = 0; i < 4; i++) {
                    float wv = wrow[i];
                    s0[i] += x0 * wv;
                    s1[i] += x1 * wv;
                }
            }
            #pragma unroll
            for (int i = 0; i < 4; i++) {
                Ps[l0 * PPAD + kq * 4 + i]       = s0[i];
                Ps[(l0 + 1) * PPAD + kq * 4 + i] = s1[i];
            }
        }
        __syncthreads();
        // ---- online softmax update: warp w owns codes w4..w4+3, lanes span rows ----
        {
            #pragma unroll
            for (int i = 0; i < 4; i++) {
                int k = w4 + i;
                float v0 = Ps[lane * PPAD + k];
                float v1 = Ps[(lane + 32) * PPAD + k];
                float mx = fmaxf(v0, v1);
                #pragma unroll
                for (int off = 16; off > 0; off >>= 1)
                    mx = fmaxf(mx, __shfl_xor_sync(0xffffffffu, mx, off));
                float mold = Sm[k];
                float mnew = fmaxf(mold, mx);
                float p0 = __expf(v0 - mnew), p1 = __expf(v1 - mnew);
                Ps[lane * PPAD + k]        = p0;
                Ps[(lane + 32) * PPAD + k] = p1;
                float sm = p0 + p1;
                #pragma unroll
                for (int off = 16; off > 0; off >>= 1)
                    sm += __shfl_xor_sync(0xffffffffu, sm, off);
                if (lane == 0) {
                    float f = __expf(mold - mnew);   // exp(-inf)=0 on first subtile
                    Sf[k] = f;
                    Ss[k] = Ss[k] * f + sm;
                    Sm[k] = mnew;
                }
            }
        }
        __syncthreads();
        // ---- rescale + accumulate ----
        {
            float f0 = Sf[w4], f1 = Sf[w4 + 1], f2 = Sf[w4 + 2], f3 = Sf[w4 + 3];
            #pragma unroll
            for (int j = 0; j < 8; j++) {
                C[0][j] *= f0; C[1][j] *= f1; C[2][j] *= f2; C[3][j] *= f3;
            }
            #pragma unroll 2
            for (int l = 0; l < ST; l++) {
                float p0 = Ps[l * PPAD + w4];
                float p1 = Ps[l * PPAD + w4 + 1];
                float p2 = Ps[l * PPAD + w4 + 2];
                float p3 = Ps[l * PPAD + w4 + 3];
                const float* xr = Xs + l * XPAD + lane;
                #pragma unroll
                for (int j = 0; j < 8; j++) {
                    float xv = xr[j * 32];
                    C[0][j] += p0 * xv;
                    C[1][j] += p1 * xv;
                    C[2][j] += p2 * xv;
                    C[3][j] += p3 * xv;
                }
            }
        }
    }
    __syncthreads();
    // ---- write partials ----
    {
        float* Co = g_partC + ((size_t)(b * NCHUNK + c) * KK) * DD;
        #pragma unroll
        for (int i = 0; i < 4; i++)
            #pragma unroll
            for (int j = 0; j < 8; j++)
                Co[(w4 + i) * DD + lane + 32 * j] = C[i][j];
        if (t < KK) {
            g_partM[(b * NCHUNK + c) * KK + t] = Sm[t];
            g_partS[(b * NCHUNK + c) * KK + t] = Ss[t];
        }
    }
}

// Combine 8 chunk-partials per (b, k): C = sum_c C_c * exp(m_c - M) / S
__global__ void combine_kernel(float* __restrict__ out) {
    const int bk = blockIdx.x;
    const int b = bk >> 5, k = bk & 31;
    const int d = threadIdx.x;
    float mc[NCHUNK], sc[NCHUNK];
    float M = -INFINITY;
    #pragma unroll
    for (int c = 0; c < NCHUNK; c++) {
        mc[c] = g_partM[(b * NCHUNK + c) * KK + k];
        M = fmaxf(M, mc[c]);
    }
    float S = 0.f;
    #pragma unroll
    for (int c = 0; c < NCHUNK; c++) {
        sc[c] = __expf(mc[c] - M);
        S += g_partS[(b * NCHUNK + c) * KK + k] * sc[c];
    }
    float inv = 1.f / S;
    float acc = 0.f;
    #pragma unroll
    for (int c = 0; c < NCHUNK; c++)
        acc += g_partC[((size_t)(b * NCHUNK + c) * KK + k) * DD + d] * sc[c];
    out[((size_t)b * KK + k) * DD + d] = acc * inv;
}

extern "C" void kernel_launch(void* const* d_in, const int* in_sizes, int n_in,
                              void* d_out, int out_size) {
    const float* X = (const float*)d_in[0];   // rev_repr (64, 2048, 256) f32
    const float* W = (const float*)d_in[1];   // W_codes  (32, 256) f32
    float* out = (float*)d_out;               // contexts (64, 32, 256) f32

    const int smem_bytes = (DD * WPAD + ST * XPAD + ST * PPAD) * (int)sizeof(float); // ~106 KB
    cudaFuncSetAttribute(fused_kernel, cudaFuncAttributeMaxDynamicSharedMemorySize, smem_bytes);

    dim3 grid(NCHUNK, BB);
    fused_kernel<<<grid, NTH, smem_bytes>>>(X, W);
    combine_kernel<<<BB * KK, DD>>>(out);
}